// round 1
// baseline (speedup 1.0000x reference)
#include <cuda_runtime.h>
#include <math.h>
#include <float.h>

#define SEQ     4096
#define DMODEL  1024
#define NHEADS  16
#define HSIZE   64
#define QKVDIM  3072

// Scratch (allocation-free rule: __device__ globals)
__device__ float g_qkv[(size_t)SEQ * QKVDIM];    // q|k|v per row, RoPE applied to q,k
__device__ float g_attn[(size_t)SEQ * DMODEL];   // attention output before W_o

// ---------------------------------------------------------------------------
// GEMM: C[M,N] = A[M,K] @ B[N,K]^T   (einsum 'sd,ed->se')
// BM=BN=128, BK=16, 256 threads, 8x8 microtile per thread.
// ROPE=true: fused RoPE epilogue on columns < 2048 (q and k blocks).
// ---------------------------------------------------------------------------
template<bool ROPE>
__global__ __launch_bounds__(256)
void gemm_kernel(const float* __restrict__ A, const float* __restrict__ B,
                 float* __restrict__ C, const int* __restrict__ pos,
                 int M, int N, int K)
{
    __shared__ float As[16][128];
    __shared__ float Bs[16][128];

    const int tid = threadIdx.x;
    const int tx  = tid & 15;        // 0..15 -> 8 output cols each
    const int ty  = tid >> 4;        // 0..15 -> 8 output rows each
    const int m0  = blockIdx.y * 128;
    const int n0  = blockIdx.x * 128;

    const int lr = tid >> 2;         // 0..63
    const int lc = (tid & 3) << 2;   // 0,4,8,12

    float acc[8][8];
#pragma unroll
    for (int i = 0; i < 8; i++)
#pragma unroll
        for (int j = 0; j < 8; j++) acc[i][j] = 0.f;

    const float* Aptr = A + (size_t)(m0 + lr) * K + lc;
    const float* Bptr = B + (size_t)(n0 + lr) * K + lc;

    for (int k0 = 0; k0 < K; k0 += 16) {
        float4 a0 = *(const float4*)(Aptr + k0);
        float4 a1 = *(const float4*)(Aptr + (size_t)64 * K + k0);
        float4 b0 = *(const float4*)(Bptr + k0);
        float4 b1 = *(const float4*)(Bptr + (size_t)64 * K + k0);

        __syncthreads();
        As[lc + 0][lr]      = a0.x; As[lc + 1][lr]      = a0.y;
        As[lc + 2][lr]      = a0.z; As[lc + 3][lr]      = a0.w;
        As[lc + 0][lr + 64] = a1.x; As[lc + 1][lr + 64] = a1.y;
        As[lc + 2][lr + 64] = a1.z; As[lc + 3][lr + 64] = a1.w;
        Bs[lc + 0][lr]      = b0.x; Bs[lc + 1][lr]      = b0.y;
        Bs[lc + 2][lr]      = b0.z; Bs[lc + 3][lr]      = b0.w;
        Bs[lc + 0][lr + 64] = b1.x; Bs[lc + 1][lr + 64] = b1.y;
        Bs[lc + 2][lr + 64] = b1.z; Bs[lc + 3][lr + 64] = b1.w;
        __syncthreads();

#pragma unroll
        for (int kk = 0; kk < 16; kk++) {
            float ar[8], br[8];
            *(float4*)&ar[0] = *(const float4*)&As[kk][ty * 8];
            *(float4*)&ar[4] = *(const float4*)&As[kk][ty * 8 + 4];
            *(float4*)&br[0] = *(const float4*)&Bs[kk][tx * 8];
            *(float4*)&br[4] = *(const float4*)&Bs[kk][tx * 8 + 4];
#pragma unroll
            for (int i = 0; i < 8; i++)
#pragma unroll
                for (int j = 0; j < 8; j++)
                    acc[i][j] = fmaf(ar[i], br[j], acc[i][j]);
        }
    }

    if (ROPE && n0 < 2 * DMODEL) {
        // Fused RoPE: cols n0+tx*8+{0..7} are 4 even/odd pairs; head dim = n & 63.
        float invf[4];
#pragma unroll
        for (int jj = 0; jj < 4; jj++) {
            int n    = n0 + tx * 8 + jj * 2;
            int kidx = (n & 63) >> 1;
            invf[jj] = 1.0f / powf(10000.0f, (2.0f * (float)kidx) / 64.0f);
        }
#pragma unroll
        for (int i = 0; i < 8; i++) {
            int   m = m0 + ty * 8 + i;
            float p = (float)pos[m];
#pragma unroll
            for (int jj = 0; jj < 4; jj++) {
                float ang = p * invf[jj];     // f32 product, matches reference quantization
                float sn, cs;
                sincosf(ang, &sn, &cs);
                float e = acc[i][2 * jj], o = acc[i][2 * jj + 1];
                acc[i][2 * jj]     = e * cs - o * sn;
                acc[i][2 * jj + 1] = o * cs + e * sn;
            }
        }
    }

#pragma unroll
    for (int i = 0; i < 8; i++) {
        float* cp = C + (size_t)(m0 + ty * 8 + i) * N + n0 + tx * 8;
        *(float4*)cp       = make_float4(acc[i][0], acc[i][1], acc[i][2], acc[i][3]);
        *((float4*)cp + 1) = make_float4(acc[i][4], acc[i][5], acc[i][6], acc[i][7]);
    }
}

// ---------------------------------------------------------------------------
// Causal flash attention, one block per (64-query tile, head).
// 256 threads = 16x16; each thread: 4 query rows x 4 cols.
// smem: Qs/Ks/Vs/Ss as [64][65] f32 (pad 65 for bank spread).
// ---------------------------------------------------------------------------
#define ATT_PAD 65
#define ATT_SMEM (4 * 64 * ATT_PAD * (int)sizeof(float))

__global__ __launch_bounds__(256)
void attn_kernel()
{
    extern __shared__ float sm[];
    float* Qs = sm;
    float* Ks = sm + 64 * ATT_PAD;
    float* Vs = sm + 2 * 64 * ATT_PAD;
    float* Ss = sm + 3 * 64 * ATT_PAD;

    const int h   = blockIdx.y;
    const int qt  = blockIdx.x;
    const int tid = threadIdx.x;
    const int tx  = tid & 15;
    const int ty  = tid >> 4;

    // Load Q tile (RoPE already applied by GEMM1 epilogue)
    const float* qbase = g_qkv + (size_t)qt * 64 * QKVDIM + h * HSIZE;
#pragma unroll
    for (int t = 0; t < 4; t++) {
        int idx = tid + t * 256;             // 1024 float4 total
        int r   = idx >> 4;
        int c   = (idx & 15) << 2;
        float4 v = *(const float4*)(qbase + (size_t)r * QKVDIM + c);
        float* q = &Qs[r * ATT_PAD + c];
        q[0] = v.x; q[1] = v.y; q[2] = v.z; q[3] = v.w;
    }

    float m_r[4], l_r[4], acc[4][4];
#pragma unroll
    for (int i = 0; i < 4; i++) {
        m_r[i] = -FLT_MAX; l_r[i] = 0.f;
#pragma unroll
        for (int j = 0; j < 4; j++) acc[i][j] = 0.f;
    }
    __syncthreads();

    for (int kt = 0; kt <= qt; kt++) {
        const float* kbase = g_qkv + (size_t)kt * 64 * QKVDIM + DMODEL + h * HSIZE;
#pragma unroll
        for (int t = 0; t < 4; t++) {
            int idx = tid + t * 256;
            int r   = idx >> 4;
            int c   = (idx & 15) << 2;
            float4 kv = *(const float4*)(kbase + (size_t)r * QKVDIM + c);
            float4 vv = *(const float4*)(kbase + DMODEL + (size_t)r * QKVDIM + c);
            float* kd = &Ks[r * ATT_PAD + c];
            float* vd = &Vs[r * ATT_PAD + c];
            kd[0] = kv.x; kd[1] = kv.y; kd[2] = kv.z; kd[3] = kv.w;
            vd[0] = vv.x; vd[1] = vv.y; vd[2] = vv.z; vd[3] = vv.w;
        }
        __syncthreads();

        // S = (Q K^T) * scale, masked on the diagonal tile
        float s[4][4];
#pragma unroll
        for (int i = 0; i < 4; i++)
#pragma unroll
            for (int j = 0; j < 4; j++) s[i][j] = 0.f;

#pragma unroll 8
        for (int dd = 0; dd < 64; dd++) {
            float qv[4], kv[4];
#pragma unroll
            for (int i = 0; i < 4; i++) qv[i] = Qs[(ty * 4 + i) * ATT_PAD + dd];
#pragma unroll
            for (int j = 0; j < 4; j++) kv[j] = Ks[(tx * 4 + j) * ATT_PAD + dd];
#pragma unroll
            for (int i = 0; i < 4; i++)
#pragma unroll
                for (int j = 0; j < 4; j++)
                    s[i][j] = fmaf(qv[i], kv[j], s[i][j]);
        }

        const bool diag = (kt == qt);
#pragma unroll
        for (int i = 0; i < 4; i++) {
#pragma unroll
            for (int j = 0; j < 4; j++) {
                float v = s[i][j] * 0.125f;                   // 1/sqrt(64)
                if (diag && (tx * 4 + j > ty * 4 + i)) v = -FLT_MAX;
                s[i][j] = v;
            }
            // row max across the 16 tx lanes (same half-warp)
            float rm = fmaxf(fmaxf(s[i][0], s[i][1]), fmaxf(s[i][2], s[i][3]));
            rm = fmaxf(rm, __shfl_xor_sync(0xffffffffu, rm, 1));
            rm = fmaxf(rm, __shfl_xor_sync(0xffffffffu, rm, 2));
            rm = fmaxf(rm, __shfl_xor_sync(0xffffffffu, rm, 4));
            rm = fmaxf(rm, __shfl_xor_sync(0xffffffffu, rm, 8));

            float mn   = fmaxf(m_r[i], rm);
            float corr = __expf(m_r[i] - mn);
            m_r[i] = mn;

            float rs = 0.f;
#pragma unroll
            for (int j = 0; j < 4; j++) {
                float p = __expf(s[i][j] - mn);
                s[i][j] = p;
                rs += p;
            }
            rs += __shfl_xor_sync(0xffffffffu, rs, 1);
            rs += __shfl_xor_sync(0xffffffffu, rs, 2);
            rs += __shfl_xor_sync(0xffffffffu, rs, 4);
            rs += __shfl_xor_sync(0xffffffffu, rs, 8);

            l_r[i] = l_r[i] * corr + rs;
#pragma unroll
            for (int j = 0; j < 4; j++) acc[i][j] *= corr;

            float* srow = &Ss[(ty * 4 + i) * ATT_PAD + tx * 4];
            srow[0] = s[i][0]; srow[1] = s[i][1]; srow[2] = s[i][2]; srow[3] = s[i][3];
        }
        __syncthreads();

        // O += P @ V
#pragma unroll 8
        for (int kk = 0; kk < 64; kk++) {
            float pv[4], vv[4];
#pragma unroll
            for (int i = 0; i < 4; i++) pv[i] = Ss[(ty * 4 + i) * ATT_PAD + kk];
#pragma unroll
            for (int j = 0; j < 4; j++) vv[j] = Vs[kk * ATT_PAD + tx * 4 + j];
#pragma unroll
            for (int i = 0; i < 4; i++)
#pragma unroll
                for (int j = 0; j < 4; j++)
                    acc[i][j] = fmaf(pv[i], vv[j], acc[i][j]);
        }
        __syncthreads();
    }

#pragma unroll
    for (int i = 0; i < 4; i++) {
        int   qg  = qt * 64 + ty * 4 + i;
        float inv = 1.0f / l_r[i];
        float* o  = g_attn + (size_t)qg * DMODEL + h * HSIZE + tx * 4;
        o[0] = acc[i][0] * inv; o[1] = acc[i][1] * inv;
        o[2] = acc[i][2] * inv; o[3] = acc[i][3] * inv;
    }
}

// ---------------------------------------------------------------------------
extern "C" void kernel_launch(void* const* d_in, const int* in_sizes, int n_in,
                              void* d_out, int out_size)
{
    const float* x    = (const float*)d_in[0];
    const int*   pos  = (const int*)  d_in[1];
    const float* Wqkv = (const float*)d_in[2];
    const float* Wo   = (const float*)d_in[3];
    float*       out  = (float*)d_out;

    float *qkv_ptr, *attn_ptr;
    cudaGetSymbolAddress((void**)&qkv_ptr,  g_qkv);
    cudaGetSymbolAddress((void**)&attn_ptr, g_attn);

    // 1) QKV projection + fused RoPE on q,k
    gemm_kernel<true><<<dim3(QKVDIM / 128, SEQ / 128), 256>>>(
        x, Wqkv, qkv_ptr, pos, SEQ, QKVDIM, DMODEL);

    // 2) Causal flash attention
    cudaFuncSetAttribute(attn_kernel,
                         cudaFuncAttributeMaxDynamicSharedMemorySize, ATT_SMEM);
    attn_kernel<<<dim3(SEQ / 64, NHEADS), 256, ATT_SMEM>>>();

    // 3) Output projection
    gemm_kernel<false><<<dim3(DMODEL / 128, SEQ / 128), 256>>>(
        attn_ptr, Wo, out, nullptr, SEQ, DMODEL, DMODEL);
}

// round 3
// speedup vs baseline: 2.8061x; 2.8061x over previous
#include <cuda_runtime.h>
#include <cuda_bf16.h>
#include <math.h>
#include <float.h>
#include <stdint.h>

#define SEQ     4096
#define DMODEL  1024
#define NHEADS  16
#define HSIZE   64
#define QKVDIM  3072

// ---------------------------------------------------------------------------
// Scratch (__device__ globals; allocation-free rule)
// ---------------------------------------------------------------------------
__device__ __nv_bfloat16 g_xhi  [(size_t)SEQ * DMODEL];
__device__ __nv_bfloat16 g_xlo  [(size_t)SEQ * DMODEL];
__device__ __nv_bfloat16 g_w1hi [(size_t)QKVDIM * DMODEL];
__device__ __nv_bfloat16 g_w1lo [(size_t)QKVDIM * DMODEL];
__device__ __nv_bfloat16 g_w2hi [(size_t)DMODEL * DMODEL];
__device__ __nv_bfloat16 g_w2lo [(size_t)DMODEL * DMODEL];
__device__ __nv_bfloat16 g_qkvhi[(size_t)SEQ * QKVDIM];   // q(pre-scaled)|k|v, RoPE'd, split
__device__ __nv_bfloat16 g_qkvlo[(size_t)SEQ * QKVDIM];
__device__ __nv_bfloat16 g_ahi  [(size_t)SEQ * DMODEL];   // attention out, split
__device__ __nv_bfloat16 g_alo  [(size_t)SEQ * DMODEL];
__device__ float g_cos[(size_t)SEQ * 32];
__device__ float g_sin[(size_t)SEQ * 32];

// ---------------------------------------------------------------------------
// mma.sync / ldmatrix helpers (base-ISA, works on .target sm_103)
// ---------------------------------------------------------------------------
__device__ __forceinline__ uint32_t smem_u32(const void* p) {
    uint32_t a;
    asm("{ .reg .u64 t; cvta.to.shared.u64 t, %1; cvt.u32.u64 %0, t; }" : "=r"(a) : "l"(p));
    return a;
}
__device__ __forceinline__ void mma_bf16(float d[4], const uint32_t a[4],
                                         uint32_t b0, uint32_t b1) {
    asm volatile("mma.sync.aligned.m16n8k16.row.col.f32.bf16.bf16.f32 "
        "{%0,%1,%2,%3}, {%4,%5,%6,%7}, {%8,%9}, {%0,%1,%2,%3};"
        : "+f"(d[0]), "+f"(d[1]), "+f"(d[2]), "+f"(d[3])
        : "r"(a[0]), "r"(a[1]), "r"(a[2]), "r"(a[3]), "r"(b0), "r"(b1));
}
__device__ __forceinline__ void ldsm_x4(uint32_t r[4], uint32_t addr) {
    asm volatile("ldmatrix.sync.aligned.m8n8.x4.shared.b16 {%0,%1,%2,%3}, [%4];"
        : "=r"(r[0]), "=r"(r[1]), "=r"(r[2]), "=r"(r[3]) : "r"(addr));
}
__device__ __forceinline__ void ldsm_x4_t(uint32_t r[4], uint32_t addr) {
    asm volatile("ldmatrix.sync.aligned.m8n8.x4.trans.shared.b16 {%0,%1,%2,%3}, [%4];"
        : "=r"(r[0]), "=r"(r[1]), "=r"(r[2]), "=r"(r[3]) : "r"(addr));
}
// Split a pair of fp32 into packed bf16x2 hi and lo (x -> low half, y -> high half)
__device__ __forceinline__ void split2(float x, float y, uint32_t& h, uint32_t& l) {
    __nv_bfloat16 hx = __float2bfloat16_rn(x), hy = __float2bfloat16_rn(y);
    __nv_bfloat16 lx = __float2bfloat16_rn(x - __bfloat162float(hx));
    __nv_bfloat16 ly = __float2bfloat16_rn(y - __bfloat162float(hy));
    __nv_bfloat162 hh(hx, hy), ll(lx, ly);
    h = *(uint32_t*)&hh;
    l = *(uint32_t*)&ll;
}

// ---------------------------------------------------------------------------
// Prep kernels
// ---------------------------------------------------------------------------
__global__ void k_split(const float* __restrict__ in, __nv_bfloat16* __restrict__ hi,
                        __nv_bfloat16* __restrict__ lo, int n4)
{
    int i = blockIdx.x * blockDim.x + threadIdx.x;
    if (i >= n4) return;
    float4 v = ((const float4*)in)[i];
    uint32_t h0, l0, h1, l1;
    split2(v.x, v.y, h0, l0);
    split2(v.z, v.w, h1, l1);
    ((uint32_t*)hi)[2 * i]     = h0;
    ((uint32_t*)hi)[2 * i + 1] = h1;
    ((uint32_t*)lo)[2 * i]     = l0;
    ((uint32_t*)lo)[2 * i + 1] = l1;
}

__global__ void k_rope_tab(const int* __restrict__ pos)
{
    int i = blockIdx.x * blockDim.x + threadIdx.x;
    if (i >= SEQ * 32) return;
    int m = i >> 5, k = i & 31;
    float invf = 1.0f / powf(10000.0f, (2.0f * (float)k) / 64.0f);
    float ang = (float)pos[m] * invf;
    float sn, cs;
    sincosf(ang, &sn, &cs);
    g_cos[i] = cs; g_sin[i] = sn;
}

// ---------------------------------------------------------------------------
// Projection GEMM via mma.sync bf16 split: C[M,N] = A[M,K] @ B[N,K]^T
// CTA 128x128, BK=32, 8 warps (2m x 4n), warp tile 64x32.
// EPI==1: RoPE + q-prescale + split-store to Chi/Clo (QKV projection)
// EPI==0: fp32 store to Cf (output projection)
// ---------------------------------------------------------------------------
#define PJS 40   // smem row stride (elements) -> 80B, conflict-free ldmatrix

template<int EPI>
__global__ __launch_bounds__(256)
void mma_gemm(const __nv_bfloat16* __restrict__ Ahi, const __nv_bfloat16* __restrict__ Alo,
              const __nv_bfloat16* __restrict__ Bhi, const __nv_bfloat16* __restrict__ Blo,
              float* __restrict__ Cf, __nv_bfloat16* __restrict__ Chi,
              __nv_bfloat16* __restrict__ Clo, int M, int N, int K)
{
    __shared__ __nv_bfloat16 sAh[128 * PJS], sAl[128 * PJS];
    __shared__ __nv_bfloat16 sBh[128 * PJS], sBl[128 * PJS];

    const int tid  = threadIdx.x;
    const int lane = tid & 31, wid = tid >> 5;
    const int m0 = blockIdx.y * 128, n0 = blockIdx.x * 128;
    const int wm = (wid & 1) * 64, wn = (wid >> 1) * 32;

    const uint32_t sAh_u = smem_u32(sAh), sAl_u = smem_u32(sAl);
    const uint32_t sBh_u = smem_u32(sBh), sBl_u = smem_u32(sBl);

    // per-lane ldmatrix address components
    const int arow = lane & 15,                    acol = (lane & 16) ? 8 : 0;
    const int brow = (lane & 7) + ((lane & 16) ? 8 : 0), bcol = (lane & 8) ? 8 : 0;

    float acc[4][4][4];
#pragma unroll
    for (int a = 0; a < 4; a++)
#pragma unroll
        for (int b = 0; b < 4; b++)
#pragma unroll
            for (int c = 0; c < 4; c++) acc[a][b][c] = 0.f;

    for (int kc = 0; kc < K; kc += 32) {
        __syncthreads();
#pragma unroll
        for (int u = 0; u < 2; u++) {
            int id = tid + u * 256;            // 512 x 16B chunks per array
            int r = id >> 2, cs = (id & 3) * 8;
            int so = r * PJS + cs;
            size_t ga = (size_t)(m0 + r) * K + kc + cs;
            size_t gb = (size_t)(n0 + r) * K + kc + cs;
            *(uint4*)(&sAh[so]) = *(const uint4*)(Ahi + ga);
            *(uint4*)(&sAl[so]) = *(const uint4*)(Alo + ga);
            *(uint4*)(&sBh[so]) = *(const uint4*)(Bhi + gb);
            *(uint4*)(&sBl[so]) = *(const uint4*)(Blo + gb);
        }
        __syncthreads();

#pragma unroll
        for (int ks = 0; ks < 2; ks++) {
            const int k0 = ks * 16;
            uint32_t ah[4][4], al[4][4];
#pragma unroll
            for (int mf = 0; mf < 4; mf++) {
                uint32_t off = (uint32_t)(((wm + mf * 16 + arow) * PJS + k0 + acol) * 2);
                ldsm_x4(ah[mf], sAh_u + off);
                ldsm_x4(al[mf], sAl_u + off);
            }
#pragma unroll
            for (int np = 0; np < 2; np++) {
                uint32_t bh[4], bl[4];
                uint32_t off = (uint32_t)(((wn + np * 16 + brow) * PJS + k0 + bcol) * 2);
                ldsm_x4(bh, sBh_u + off);
                ldsm_x4(bl, sBl_u + off);
#pragma unroll
                for (int sel = 0; sel < 2; sel++) {
                    const int nf = np * 2 + sel;
                    uint32_t bh0 = bh[sel * 2], bh1 = bh[sel * 2 + 1];
                    uint32_t bl0 = bl[sel * 2], bl1 = bl[sel * 2 + 1];
#pragma unroll
                    for (int mf = 0; mf < 4; mf++) {
                        mma_bf16(acc[mf][nf], ah[mf], bh0, bh1);
                        mma_bf16(acc[mf][nf], ah[mf], bl0, bl1);
                        mma_bf16(acc[mf][nf], al[mf], bh0, bh1);
                    }
                }
            }
        }
    }

    // epilogue
#pragma unroll
    for (int mf = 0; mf < 4; mf++) {
#pragma unroll
        for (int hf = 0; hf < 2; hf++) {
            const int row = m0 + wm + mf * 16 + (lane >> 2) + hf * 8;
#pragma unroll
            for (int nf = 0; nf < 4; nf++) {
                const int col = n0 + wn + nf * 8 + (lane & 3) * 2;
                float v0 = acc[mf][nf][hf * 2], v1 = acc[mf][nf][hf * 2 + 1];
                if (EPI == 1) {
                    if (col < 2 * DMODEL) {
                        int kidx = (col & 63) >> 1;
                        float cs = g_cos[row * 32 + kidx];
                        float sn = g_sin[row * 32 + kidx];
                        float e = v0, o = v1;
                        v0 = e * cs - o * sn;
                        v1 = o * cs + e * sn;
                        if (col < DMODEL) { v0 *= 0.125f; v1 *= 0.125f; }  // fold 1/sqrt(64)
                    }
                    uint32_t h, l;
                    split2(v0, v1, h, l);
                    *(uint32_t*)(Chi + (size_t)row * N + col) = h;
                    *(uint32_t*)(Clo + (size_t)row * N + col) = l;
                } else {
                    *(float2*)(Cf + (size_t)row * N + col) = make_float2(v0, v1);
                }
            }
        }
    }
}

// ---------------------------------------------------------------------------
// Causal flash attention via mma.sync bf16 split.
// Block = (64-query tile, head), 4 warps; warp owns 16 q-rows.
// S and O live in mma accumulators; P rebuilt in-register (FA2 layout trick).
// ---------------------------------------------------------------------------
#define AS 72   // attention smem row stride (elements) -> 144B, conflict-free
#define ATT_SMEM (6 * 64 * AS * (int)sizeof(__nv_bfloat16))

__global__ __launch_bounds__(128)
void attn_mma()
{
    extern __shared__ __nv_bfloat16 sm[];
    __nv_bfloat16* Qh = sm;
    __nv_bfloat16* Ql = sm + 1 * 64 * AS;
    __nv_bfloat16* Kh = sm + 2 * 64 * AS;
    __nv_bfloat16* Kl = sm + 3 * 64 * AS;
    __nv_bfloat16* Vh = sm + 4 * 64 * AS;
    __nv_bfloat16* Vl = sm + 5 * 64 * AS;

    const int h   = blockIdx.y;
    const int qt  = blockIdx.x;
    const int tid = threadIdx.x;
    const int lane = tid & 31, w = tid >> 5;

    const uint32_t Qh_u = smem_u32(Qh), Ql_u = smem_u32(Ql);
    const uint32_t Kh_u = smem_u32(Kh), Kl_u = smem_u32(Kl);
    const uint32_t Vh_u = smem_u32(Vh), Vl_u = smem_u32(Vl);

    // Load Q tile (already RoPE'd, scaled, split)
    const size_t qbase = (size_t)(qt * 64) * QKVDIM + h * HSIZE;
#pragma unroll
    for (int u = 0; u < 4; u++) {
        int id = tid + u * 128;               // 512 chunks
        int r = id >> 3, c = (id & 7) * 8;
        size_t g = qbase + (size_t)r * QKVDIM + c;
        *(uint4*)(&Qh[r * AS + c]) = *(const uint4*)(g_qkvhi + g);
        *(uint4*)(&Ql[r * AS + c]) = *(const uint4*)(g_qkvlo + g);
    }
    __syncthreads();

    const int arow = lane & 15,                    acol = (lane & 16) ? 8 : 0;
    const int brow = (lane & 7) + ((lane & 16) ? 8 : 0), bcol = (lane & 8) ? 8 : 0;

    // Q a-fragments, resident for the whole block
    uint32_t qfh[4][4], qfl[4][4];
#pragma unroll
    for (int t = 0; t < 4; t++) {
        uint32_t off = (uint32_t)(((w * 16 + arow) * AS + t * 16 + acol) * 2);
        ldsm_x4(qfh[t], Qh_u + off);
        ldsm_x4(qfl[t], Ql_u + off);
    }

    float o[8][4];
#pragma unroll
    for (int i = 0; i < 8; i++)
#pragma unroll
        for (int j = 0; j < 4; j++) o[i][j] = 0.f;
    float mr[2] = { -FLT_MAX, -FLT_MAX };
    float lr[2] = { 0.f, 0.f };

    for (int kt = 0; kt <= qt; kt++) {
        const size_t kb = (size_t)(kt * 64) * QKVDIM + DMODEL + h * HSIZE;
        const size_t vb = kb + DMODEL;
#pragma unroll
        for (int u = 0; u < 4; u++) {
            int id = tid + u * 128;
            int r = id >> 3, c = (id & 7) * 8;
            size_t gk = kb + (size_t)r * QKVDIM + c;
            size_t gv = vb + (size_t)r * QKVDIM + c;
            *(uint4*)(&Kh[r * AS + c]) = *(const uint4*)(g_qkvhi + gk);
            *(uint4*)(&Kl[r * AS + c]) = *(const uint4*)(g_qkvlo + gk);
            *(uint4*)(&Vh[r * AS + c]) = *(const uint4*)(g_qkvhi + gv);
            *(uint4*)(&Vl[r * AS + c]) = *(const uint4*)(g_qkvlo + gv);
        }
        __syncthreads();

        // S = Q' K^T (scale pre-folded into Q)
        float s[8][4];
#pragma unroll
        for (int i = 0; i < 8; i++)
#pragma unroll
            for (int j = 0; j < 4; j++) s[i][j] = 0.f;

#pragma unroll
        for (int t = 0; t < 4; t++) {
#pragma unroll
            for (int np = 0; np < 4; np++) {
                uint32_t bh[4], bl[4];
                uint32_t off = (uint32_t)(((np * 16 + brow) * AS + t * 16 + bcol) * 2);
                ldsm_x4(bh, Kh_u + off);
                ldsm_x4(bl, Kl_u + off);
#pragma unroll
                for (int sel = 0; sel < 2; sel++) {
                    const int nf = np * 2 + sel;
                    uint32_t b0h = bh[sel * 2], b1h = bh[sel * 2 + 1];
                    uint32_t b0l = bl[sel * 2], b1l = bl[sel * 2 + 1];
                    mma_bf16(s[nf], qfh[t], b0h, b1h);
                    mma_bf16(s[nf], qfh[t], b0l, b1l);
                    mma_bf16(s[nf], qfl[t], b0h, b1h);
                }
            }
        }

        // causal mask on the diagonal tile
        if (kt == qt) {
            const int r0 = w * 16 + (lane >> 2);
            const int r1 = r0 + 8;
#pragma unroll
            for (int nf = 0; nf < 8; nf++) {
                const int c0 = nf * 8 + (lane & 3) * 2;
                if (c0     > r0) s[nf][0] = -FLT_MAX;
                if (c0 + 1 > r0) s[nf][1] = -FLT_MAX;
                if (c0     > r1) s[nf][2] = -FLT_MAX;
                if (c0 + 1 > r1) s[nf][3] = -FLT_MAX;
            }
        }

        // online softmax per row-half
#pragma unroll
        for (int hf = 0; hf < 2; hf++) {
            float rm = -FLT_MAX;
#pragma unroll
            for (int nf = 0; nf < 8; nf++)
                rm = fmaxf(rm, fmaxf(s[nf][hf * 2], s[nf][hf * 2 + 1]));
            rm = fmaxf(rm, __shfl_xor_sync(0xffffffffu, rm, 1));
            rm = fmaxf(rm, __shfl_xor_sync(0xffffffffu, rm, 2));

            float mn   = fmaxf(mr[hf], rm);
            float corr = __expf(mr[hf] - mn);
            mr[hf] = mn;

            float rs = 0.f;
#pragma unroll
            for (int nf = 0; nf < 8; nf++) {
                float p0 = __expf(s[nf][hf * 2]     - mn);
                float p1 = __expf(s[nf][hf * 2 + 1] - mn);
                s[nf][hf * 2]     = p0;
                s[nf][hf * 2 + 1] = p1;
                rs += p0 + p1;
            }
            rs += __shfl_xor_sync(0xffffffffu, rs, 1);
            rs += __shfl_xor_sync(0xffffffffu, rs, 2);

            lr[hf] = lr[hf] * corr + rs;
#pragma unroll
            for (int df = 0; df < 8; df++) {
                o[df][hf * 2]     *= corr;
                o[df][hf * 2 + 1] *= corr;
            }
        }

        // O += P V  (P from S fragments, split in-register)
#pragma unroll
        for (int t = 0; t < 4; t++) {
            uint32_t ph[4], pl[4];
            split2(s[2 * t][0],     s[2 * t][1],     ph[0], pl[0]);
            split2(s[2 * t][2],     s[2 * t][3],     ph[1], pl[1]);
            split2(s[2 * t + 1][0], s[2 * t + 1][1], ph[2], pl[2]);
            split2(s[2 * t + 1][2], s[2 * t + 1][3], ph[3], pl[3]);
#pragma unroll
            for (int np = 0; np < 4; np++) {
                uint32_t vh4[4], vl4[4];
                uint32_t off = (uint32_t)(((t * 16 + arow) * AS + np * 16 + acol) * 2);
                ldsm_x4_t(vh4, Vh_u + off);
                ldsm_x4_t(vl4, Vl_u + off);
#pragma unroll
                for (int sel = 0; sel < 2; sel++) {
                    const int df = np * 2 + sel;
                    uint32_t v0h = vh4[sel * 2], v1h = vh4[sel * 2 + 1];
                    uint32_t v0l = vl4[sel * 2], v1l = vl4[sel * 2 + 1];
                    mma_bf16(o[df], ph, v0h, v1h);
                    mma_bf16(o[df], ph, v0l, v1l);
                    mma_bf16(o[df], pl, v0h, v1h);
                }
            }
        }
        __syncthreads();   // protect smem before next tile load
    }

    // epilogue: normalize, split, store for the O-projection
#pragma unroll
    for (int hf = 0; hf < 2; hf++) {
        const float inv = 1.0f / lr[hf];
        const int row = qt * 64 + w * 16 + (lane >> 2) + hf * 8;
#pragma unroll
        for (int df = 0; df < 8; df++) {
            const int col = h * 64 + df * 8 + (lane & 3) * 2;
            float v0 = o[df][hf * 2] * inv, v1 = o[df][hf * 2 + 1] * inv;
            uint32_t hh, ll;
            split2(v0, v1, hh, ll);
            *(uint32_t*)(g_ahi + (size_t)row * DMODEL + col) = hh;
            *(uint32_t*)(g_alo + (size_t)row * DMODEL + col) = ll;
        }
    }
}

// ---------------------------------------------------------------------------
extern "C" void kernel_launch(void* const* d_in, const int* in_sizes, int n_in,
                              void* d_out, int out_size)
{
    const float* x    = (const float*)d_in[0];
    const int*   pos  = (const int*)  d_in[1];
    const float* Wqkv = (const float*)d_in[2];
    const float* Wo   = (const float*)d_in[3];
    float*       out  = (float*)d_out;

    __nv_bfloat16 *xhi, *xlo, *w1hi, *w1lo, *w2hi, *w2lo, *qkvhi, *qkvlo, *ahi, *alo;
    cudaGetSymbolAddress((void**)&xhi,   g_xhi);
    cudaGetSymbolAddress((void**)&xlo,   g_xlo);
    cudaGetSymbolAddress((void**)&w1hi,  g_w1hi);
    cudaGetSymbolAddress((void**)&w1lo,  g_w1lo);
    cudaGetSymbolAddress((void**)&w2hi,  g_w2hi);
    cudaGetSymbolAddress((void**)&w2lo,  g_w2lo);
    cudaGetSymbolAddress((void**)&qkvhi, g_qkvhi);
    cudaGetSymbolAddress((void**)&qkvlo, g_qkvlo);
    cudaGetSymbolAddress((void**)&ahi,   g_ahi);
    cudaGetSymbolAddress((void**)&alo,   g_alo);

    cudaFuncSetAttribute(attn_mma,
                         cudaFuncAttributeMaxDynamicSharedMemorySize, ATT_SMEM);

    // Prep: splits + RoPE tables
    k_split<<<(SEQ * DMODEL / 4 + 255) / 256, 256>>>(x, xhi, xlo, SEQ * DMODEL / 4);
    k_split<<<(QKVDIM * DMODEL / 4 + 255) / 256, 256>>>(Wqkv, w1hi, w1lo, QKVDIM * DMODEL / 4);
    k_split<<<(DMODEL * DMODEL / 4 + 255) / 256, 256>>>(Wo, w2hi, w2lo, DMODEL * DMODEL / 4);
    k_rope_tab<<<(SEQ * 32 + 255) / 256, 256>>>(pos);

    // 1) QKV projection + RoPE + q-prescale + split store
    mma_gemm<1><<<dim3(QKVDIM / 128, SEQ / 128), 256>>>(
        xhi, xlo, w1hi, w1lo, nullptr, qkvhi, qkvlo, SEQ, QKVDIM, DMODEL);

    // 2) Causal flash attention (mma.sync, split bf16)
    attn_mma<<<dim3(SEQ / 64, NHEADS), 128, ATT_SMEM>>>();

    // 3) Output projection -> fp32 out
    mma_gemm<0><<<dim3(DMODEL / 128, SEQ / 128), 256>>>(
        ahi, alo, w2hi, w2lo, out, nullptr, nullptr, SEQ, DMODEL, DMODEL);
}

// round 4
// speedup vs baseline: 3.3419x; 1.1909x over previous
#include <cuda_runtime.h>
#include <cuda_bf16.h>
#include <math.h>
#include <float.h>
#include <stdint.h>

#define SEQ     4096
#define DMODEL  1024
#define NHEADS  16
#define HSIZE   64
#define QKVDIM  3072

// ---------------------------------------------------------------------------
// Scratch (__device__ globals; allocation-free rule)
// ---------------------------------------------------------------------------
__device__ __nv_bfloat16 g_xhi  [(size_t)SEQ * DMODEL];
__device__ __nv_bfloat16 g_xlo  [(size_t)SEQ * DMODEL];
__device__ __nv_bfloat16 g_w1hi [(size_t)QKVDIM * DMODEL];
__device__ __nv_bfloat16 g_w1lo [(size_t)QKVDIM * DMODEL];
__device__ __nv_bfloat16 g_w2hi [(size_t)DMODEL * DMODEL];
__device__ __nv_bfloat16 g_w2lo [(size_t)DMODEL * DMODEL];
__device__ __nv_bfloat16 g_qkvhi[(size_t)SEQ * QKVDIM];   // q(pre-scaled)|k|v, RoPE'd, split
__device__ __nv_bfloat16 g_qkvlo[(size_t)SEQ * QKVDIM];
__device__ __nv_bfloat16 g_ahi  [(size_t)SEQ * DMODEL];   // attention out, split
__device__ __nv_bfloat16 g_alo  [(size_t)SEQ * DMODEL];
__device__ float g_cos[(size_t)SEQ * 32];
__device__ float g_sin[(size_t)SEQ * 32];

// ---------------------------------------------------------------------------
// Helpers (base-ISA: mma.sync / ldmatrix / cp.async)
// ---------------------------------------------------------------------------
__device__ __forceinline__ uint32_t smem_u32(const void* p) {
    uint32_t a;
    asm("{ .reg .u64 t; cvta.to.shared.u64 t, %1; cvt.u32.u64 %0, t; }" : "=r"(a) : "l"(p));
    return a;
}
__device__ __forceinline__ void mma_bf16(float d[4], const uint32_t a[4],
                                         uint32_t b0, uint32_t b1) {
    asm volatile("mma.sync.aligned.m16n8k16.row.col.f32.bf16.bf16.f32 "
        "{%0,%1,%2,%3}, {%4,%5,%6,%7}, {%8,%9}, {%0,%1,%2,%3};"
        : "+f"(d[0]), "+f"(d[1]), "+f"(d[2]), "+f"(d[3])
        : "r"(a[0]), "r"(a[1]), "r"(a[2]), "r"(a[3]), "r"(b0), "r"(b1));
}
__device__ __forceinline__ void ldsm_x4(uint32_t r[4], uint32_t addr) {
    asm volatile("ldmatrix.sync.aligned.m8n8.x4.shared.b16 {%0,%1,%2,%3}, [%4];"
        : "=r"(r[0]), "=r"(r[1]), "=r"(r[2]), "=r"(r[3]) : "r"(addr));
}
__device__ __forceinline__ void ldsm_x4_t(uint32_t r[4], uint32_t addr) {
    asm volatile("ldmatrix.sync.aligned.m8n8.x4.trans.shared.b16 {%0,%1,%2,%3}, [%4];"
        : "=r"(r[0]), "=r"(r[1]), "=r"(r[2]), "=r"(r[3]) : "r"(addr));
}
__device__ __forceinline__ void split2(float x, float y, uint32_t& h, uint32_t& l) {
    __nv_bfloat16 hx = __float2bfloat16_rn(x), hy = __float2bfloat16_rn(y);
    __nv_bfloat16 lx = __float2bfloat16_rn(x - __bfloat162float(hx));
    __nv_bfloat16 ly = __float2bfloat16_rn(y - __bfloat162float(hy));
    __nv_bfloat162 hh(hx, hy), ll(lx, ly);
    h = *(uint32_t*)&hh;
    l = *(uint32_t*)&ll;
}
#define CP16(dst, src) asm volatile("cp.async.cg.shared.global [%0], [%1], 16;" \
                                    :: "r"(dst), "l"(src))
#define CP_COMMIT() asm volatile("cp.async.commit_group;" ::: "memory")
#define CP_WAIT1()  asm volatile("cp.async.wait_group 1;" ::: "memory")
#define CP_WAIT0()  asm volatile("cp.async.wait_group 0;" ::: "memory")

// 128B rows (64 bf16), XOR chunk swizzle: conflict-free for cp.async stores AND
// per-lane-addressed ldmatrix reads. row/chunk -> byte offset.
__device__ __forceinline__ uint32_t swz128(int row, int c) {
    return (uint32_t)(row * 128 + ((c ^ (row & 7)) << 4));
}

// ---------------------------------------------------------------------------
// Prep kernels
// ---------------------------------------------------------------------------
__global__ void k_split(const float* __restrict__ in, __nv_bfloat16* __restrict__ hi,
                        __nv_bfloat16* __restrict__ lo, int n4)
{
    int i = blockIdx.x * blockDim.x + threadIdx.x;
    if (i >= n4) return;
    float4 v = ((const float4*)in)[i];
    uint32_t h0, l0, h1, l1;
    split2(v.x, v.y, h0, l0);
    split2(v.z, v.w, h1, l1);
    ((uint32_t*)hi)[2 * i]     = h0;
    ((uint32_t*)hi)[2 * i + 1] = h1;
    ((uint32_t*)lo)[2 * i]     = l0;
    ((uint32_t*)lo)[2 * i + 1] = l1;
}

__global__ void k_rope_tab(const int* __restrict__ pos)
{
    int i = blockIdx.x * blockDim.x + threadIdx.x;
    if (i >= SEQ * 32) return;
    int m = i >> 5, k = i & 31;
    float invf = 1.0f / powf(10000.0f, (2.0f * (float)k) / 64.0f);
    float ang = (float)pos[m] * invf;
    float sn, cs;
    sincosf(ang, &sn, &cs);
    g_cos[i] = cs; g_sin[i] = sn;
}

// ---------------------------------------------------------------------------
// Projection GEMM (pipelined): C[M,N] = A[M,K] @ B[N,K]^T, bf16 3-product split.
// CTA 128x128, BK=64, 2-stage cp.async double buffer, 8 warps (2m x 4n).
// EPI==1: RoPE + q-prescale + split store; EPI==0: fp32 store.
// ---------------------------------------------------------------------------
#define GEMM_ARR  16384                     // 128 rows x 128B
#define GEMM_SMEM (2 * 4 * GEMM_ARR)        // 131072 B

template<int EPI>
__global__ __launch_bounds__(256)
void mma_gemm(const __nv_bfloat16* __restrict__ Ahi, const __nv_bfloat16* __restrict__ Alo,
              const __nv_bfloat16* __restrict__ Bhi, const __nv_bfloat16* __restrict__ Blo,
              float* __restrict__ Cf, __nv_bfloat16* __restrict__ Chi,
              __nv_bfloat16* __restrict__ Clo, int M, int N, int K)
{
    extern __shared__ __nv_bfloat16 dsm[];
    const uint32_t sb = smem_u32(dsm);
    const int tid = threadIdx.x, lane = tid & 31, wid = tid >> 5;
    const int m0 = blockIdx.y * 128, n0 = blockIdx.x * 128;
    const int wm = (wid & 1) * 64, wn = (wid >> 1) * 32;

    const int arow = lane & 15,                    acol = (lane & 16) ? 1 : 0;
    const int brow = (lane & 7) + ((lane & 16) ? 8 : 0), bcol = (lane & 8) ? 1 : 0;

    float acc[4][4][4];
#pragma unroll
    for (int a = 0; a < 4; a++)
#pragma unroll
        for (int b = 0; b < 4; b++)
#pragma unroll
            for (int c = 0; c < 4; c++) acc[a][b][c] = 0.f;

    const int nk = K >> 6;

    // stage loader: 4 arrays x 128 rows x 8 chunks (16B)
    auto load_stage = [&](int kc, int s) {
        const uint32_t base = sb + (uint32_t)(s * 4) * GEMM_ARR;
#pragma unroll
        for (int u = 0; u < 4; u++) {
            int id = tid + u * 256;
            int r = id >> 3, c = id & 7;
            uint32_t so = swz128(r, c);
            size_t ga = (size_t)(m0 + r) * K + kc + c * 8;
            size_t gb = (size_t)(n0 + r) * K + kc + c * 8;
            CP16(base +                so, Ahi + ga);
            CP16(base +     GEMM_ARR + so, Alo + ga);
            CP16(base + 2 * GEMM_ARR + so, Bhi + gb);
            CP16(base + 3 * GEMM_ARR + so, Blo + gb);
        }
        CP_COMMIT();
    };

    load_stage(0, 0);
    for (int kc = 0; kc < nk; kc++) {
        const int cur = kc & 1;
        if (kc + 1 < nk) { load_stage((kc + 1) << 6, cur ^ 1); CP_WAIT1(); }
        else             { CP_WAIT0(); }
        __syncthreads();

        const uint32_t ab = sb + (uint32_t)(cur * 4) * GEMM_ARR;
        const uint32_t bb = ab + 2 * GEMM_ARR;
#pragma unroll
        for (int ks = 0; ks < 4; ks++) {
            uint32_t ah[4][4], al[4][4];
#pragma unroll
            for (int mf = 0; mf < 4; mf++) {
                uint32_t off = swz128(wm + mf * 16 + arow, ks * 2 + acol);
                ldsm_x4(ah[mf], ab + off);
                ldsm_x4(al[mf], ab + GEMM_ARR + off);
            }
#pragma unroll
            for (int np = 0; np < 2; np++) {
                uint32_t bh[4], bl[4];
                uint32_t off = swz128(wn + np * 16 + brow, ks * 2 + bcol);
                ldsm_x4(bh, bb + off);
                ldsm_x4(bl, bb + GEMM_ARR + off);
#pragma unroll
                for (int sel = 0; sel < 2; sel++) {
                    const int nf = np * 2 + sel;
                    uint32_t bh0 = bh[sel * 2], bh1 = bh[sel * 2 + 1];
                    uint32_t bl0 = bl[sel * 2], bl1 = bl[sel * 2 + 1];
#pragma unroll
                    for (int mf = 0; mf < 4; mf++) {
                        mma_bf16(acc[mf][nf], ah[mf], bh0, bh1);
                        mma_bf16(acc[mf][nf], ah[mf], bl0, bl1);
                        mma_bf16(acc[mf][nf], al[mf], bh0, bh1);
                    }
                }
            }
        }
        __syncthreads();
    }

    // epilogue
#pragma unroll
    for (int mf = 0; mf < 4; mf++) {
#pragma unroll
        for (int hf = 0; hf < 2; hf++) {
            const int row = m0 + wm + mf * 16 + (lane >> 2) + hf * 8;
#pragma unroll
            for (int nf = 0; nf < 4; nf++) {
                const int col = n0 + wn + nf * 8 + (lane & 3) * 2;
                float v0 = acc[mf][nf][hf * 2], v1 = acc[mf][nf][hf * 2 + 1];
                if (EPI == 1) {
                    if (col < 2 * DMODEL) {
                        int kidx = (col & 63) >> 1;
                        float cs = g_cos[row * 32 + kidx];
                        float sn = g_sin[row * 32 + kidx];
                        float e = v0, o = v1;
                        v0 = e * cs - o * sn;
                        v1 = o * cs + e * sn;
                        if (col < DMODEL) { v0 *= 0.125f; v1 *= 0.125f; }  // 1/sqrt(64)
                    }
                    uint32_t h, l;
                    split2(v0, v1, h, l);
                    *(uint32_t*)(Chi + (size_t)row * N + col) = h;
                    *(uint32_t*)(Clo + (size_t)row * N + col) = l;
                } else {
                    *(float2*)(Cf + (size_t)row * N + col) = make_float2(v0, v1);
                }
            }
        }
    }
}

// ---------------------------------------------------------------------------
// Causal flash attention (pipelined): Q-tile 128, K-tile 64, 8 warps.
// 2-stage cp.async K/V double buffer; S,O in mma accumulators; 3-product split.
// ---------------------------------------------------------------------------
#define ATT_QARR 16384                       // 128 rows x 128B
#define ATT_KARR 8192                        // 64 rows x 128B
#define ATT_SMEM (2 * ATT_QARR + 2 * 4 * ATT_KARR)   // 98304 B

__global__ __launch_bounds__(256)
void attn_mma()
{
    extern __shared__ __nv_bfloat16 sm[];
    const uint32_t sb  = smem_u32(sm);
    const uint32_t kvb = sb + 2 * ATT_QARR;

    const int h   = blockIdx.y;
    const int qt  = gridDim.x - 1 - blockIdx.x;    // big tiles first
    const int tid = threadIdx.x;
    const int lane = tid & 31, w = tid >> 5;

    const int arow = lane & 15,                    acol = (lane & 16) ? 1 : 0;
    const int brow = (lane & 7) + ((lane & 16) ? 8 : 0), bcol = (lane & 8) ? 1 : 0;

    // async Q load (committed together with K/V stage 0)
    const size_t qbase = (size_t)(qt * 128) * QKVDIM + h * HSIZE;
#pragma unroll
    for (int u = 0; u < 4; u++) {
        int id = tid + u * 256;
        int r = id >> 3, c = id & 7;
        uint32_t so = swz128(r, c);
        size_t g = qbase + (size_t)r * QKVDIM + c * 8;
        CP16(sb + so,            g_qkvhi + g);
        CP16(sb + ATT_QARR + so, g_qkvlo + g);
    }

    auto load_kv = [&](int kt, int s) {
        const size_t kb = (size_t)(kt * 64) * QKVDIM + DMODEL + h * HSIZE;
        const size_t vb = kb + DMODEL;
        const uint32_t base = kvb + (uint32_t)(s * 4) * ATT_KARR;
#pragma unroll
        for (int u = 0; u < 2; u++) {
            int id = tid + u * 256;
            int r = id >> 3, c = id & 7;
            uint32_t so = swz128(r, c);
            size_t gk = kb + (size_t)r * QKVDIM + c * 8;
            size_t gv = vb + (size_t)r * QKVDIM + c * 8;
            CP16(base +               so, g_qkvhi + gk);
            CP16(base +     ATT_KARR + so, g_qkvlo + gk);
            CP16(base + 2 * ATT_KARR + so, g_qkvhi + gv);
            CP16(base + 3 * ATT_KARR + so, g_qkvlo + gv);
        }
        CP_COMMIT();
    };

    load_kv(0, 0);

    uint32_t qfh[4][4], qfl[4][4];
    float o[8][4];
#pragma unroll
    for (int i = 0; i < 8; i++)
#pragma unroll
        for (int j = 0; j < 4; j++) o[i][j] = 0.f;
    float mr[2] = { -FLT_MAX, -FLT_MAX };
    float lr[2] = { 0.f, 0.f };

    const int wrow = qt * 128 + w * 16;        // warp's first global q row
    const int ktmax = 2 * qt + 1;

    for (int kt = 0; kt <= ktmax; kt++) {
        const int cur = kt & 1;
        if (kt < ktmax) { load_kv(kt + 1, cur ^ 1); CP_WAIT1(); }
        else            { CP_WAIT0(); }
        __syncthreads();

        if (kt == 0) {
#pragma unroll
            for (int t = 0; t < 4; t++) {
                uint32_t off = swz128(w * 16 + arow, t * 2 + acol);
                ldsm_x4(qfh[t], sb + off);
                ldsm_x4(qfl[t], sb + ATT_QARR + off);
            }
        }

        if (kt * 64 <= wrow + 15) {            // skip fully-masked tiles per warp
            const uint32_t kbh = kvb + (uint32_t)(cur * 4) * ATT_KARR;
            const uint32_t kbl = kbh + ATT_KARR;
            const uint32_t vbh = kbh + 2 * ATT_KARR;
            const uint32_t vbl = kbh + 3 * ATT_KARR;

            float s[8][4];
#pragma unroll
            for (int i = 0; i < 8; i++)
#pragma unroll
                for (int j = 0; j < 4; j++) s[i][j] = 0.f;

            // S = Q' K^T (scale pre-folded into Q)
#pragma unroll
            for (int t = 0; t < 4; t++) {
#pragma unroll
                for (int np = 0; np < 4; np++) {
                    uint32_t bh[4], bl[4];
                    uint32_t off = swz128(np * 16 + brow, t * 2 + bcol);
                    ldsm_x4(bh, kbh + off);
                    ldsm_x4(bl, kbl + off);
#pragma unroll
                    for (int sel = 0; sel < 2; sel++) {
                        const int nf = np * 2 + sel;
                        uint32_t b0h = bh[sel * 2], b1h = bh[sel * 2 + 1];
                        uint32_t b0l = bl[sel * 2], b1l = bl[sel * 2 + 1];
                        mma_bf16(s[nf], qfh[t], b0h, b1h);
                        mma_bf16(s[nf], qfh[t], b0l, b1l);
                        mma_bf16(s[nf], qfl[t], b0h, b1h);
                    }
                }
            }

            // causal mask (only tiles crossing the diagonal)
            if (kt * 64 + 63 > wrow) {
                const int r0 = wrow + (lane >> 2), r1 = r0 + 8;
                const int cb = kt * 64 + (lane & 3) * 2;
#pragma unroll
                for (int nf = 0; nf < 8; nf++) {
                    const int c0 = cb + nf * 8;
                    if (c0     > r0) s[nf][0] = -FLT_MAX;
                    if (c0 + 1 > r0) s[nf][1] = -FLT_MAX;
                    if (c0     > r1) s[nf][2] = -FLT_MAX;
                    if (c0 + 1 > r1) s[nf][3] = -FLT_MAX;
                }
            }

            // online softmax per row-half
#pragma unroll
            for (int hf = 0; hf < 2; hf++) {
                float rm = -FLT_MAX;
#pragma unroll
                for (int nf = 0; nf < 8; nf++)
                    rm = fmaxf(rm, fmaxf(s[nf][hf * 2], s[nf][hf * 2 + 1]));
                rm = fmaxf(rm, __shfl_xor_sync(0xffffffffu, rm, 1));
                rm = fmaxf(rm, __shfl_xor_sync(0xffffffffu, rm, 2));

                float mn   = fmaxf(mr[hf], rm);
                float corr = __expf(mr[hf] - mn);
                mr[hf] = mn;

                float rs = 0.f;
#pragma unroll
                for (int nf = 0; nf < 8; nf++) {
                    float p0 = __expf(s[nf][hf * 2]     - mn);
                    float p1 = __expf(s[nf][hf * 2 + 1] - mn);
                    s[nf][hf * 2]     = p0;
                    s[nf][hf * 2 + 1] = p1;
                    rs += p0 + p1;
                }
                rs += __shfl_xor_sync(0xffffffffu, rs, 1);
                rs += __shfl_xor_sync(0xffffffffu, rs, 2);

                lr[hf] = lr[hf] * corr + rs;
#pragma unroll
                for (int df = 0; df < 8; df++) {
                    o[df][hf * 2]     *= corr;
                    o[df][hf * 2 + 1] *= corr;
                }
            }

            // O += P V (P re-split in-register; V via ldmatrix.trans)
#pragma unroll
            for (int t = 0; t < 4; t++) {
                uint32_t ph[4], pl[4];
                split2(s[2 * t][0],     s[2 * t][1],     ph[0], pl[0]);
                split2(s[2 * t][2],     s[2 * t][3],     ph[1], pl[1]);
                split2(s[2 * t + 1][0], s[2 * t + 1][1], ph[2], pl[2]);
                split2(s[2 * t + 1][2], s[2 * t + 1][3], ph[3], pl[3]);
#pragma unroll
                for (int np = 0; np < 4; np++) {
                    uint32_t vh4[4], vl4[4];
                    uint32_t off = swz128(t * 16 + arow, np * 2 + acol);
                    ldsm_x4_t(vh4, vbh + off);
                    ldsm_x4_t(vl4, vbl + off);
#pragma unroll
                    for (int sel = 0; sel < 2; sel++) {
                        const int df = np * 2 + sel;
                        uint32_t v0h = vh4[sel * 2], v1h = vh4[sel * 2 + 1];
                        uint32_t v0l = vl4[sel * 2], v1l = vl4[sel * 2 + 1];
                        mma_bf16(o[df], ph, v0h, v1h);
                        mma_bf16(o[df], ph, v0l, v1l);
                        mma_bf16(o[df], pl, v0h, v1h);
                    }
                }
            }
        }
        __syncthreads();
    }

    // epilogue: normalize, split, store for the O-projection
#pragma unroll
    for (int hf = 0; hf < 2; hf++) {
        const float inv = 1.0f / lr[hf];
        const int row = wrow + (lane >> 2) + hf * 8;
#pragma unroll
        for (int df = 0; df < 8; df++) {
            const int col = h * 64 + df * 8 + (lane & 3) * 2;
            float v0 = o[df][hf * 2] * inv, v1 = o[df][hf * 2 + 1] * inv;
            uint32_t hh, ll;
            split2(v0, v1, hh, ll);
            *(uint32_t*)(g_ahi + (size_t)row * DMODEL + col) = hh;
            *(uint32_t*)(g_alo + (size_t)row * DMODEL + col) = ll;
        }
    }
}

// ---------------------------------------------------------------------------
extern "C" void kernel_launch(void* const* d_in, const int* in_sizes, int n_in,
                              void* d_out, int out_size)
{
    const float* x    = (const float*)d_in[0];
    const int*   pos  = (const int*)  d_in[1];
    const float* Wqkv = (const float*)d_in[2];
    const float* Wo   = (const float*)d_in[3];
    float*       out  = (float*)d_out;

    __nv_bfloat16 *xhi, *xlo, *w1hi, *w1lo, *w2hi, *w2lo, *qkvhi, *qkvlo, *ahi, *alo;
    cudaGetSymbolAddress((void**)&xhi,   g_xhi);
    cudaGetSymbolAddress((void**)&xlo,   g_xlo);
    cudaGetSymbolAddress((void**)&w1hi,  g_w1hi);
    cudaGetSymbolAddress((void**)&w1lo,  g_w1lo);
    cudaGetSymbolAddress((void**)&w2hi,  g_w2hi);
    cudaGetSymbolAddress((void**)&w2lo,  g_w2lo);
    cudaGetSymbolAddress((void**)&qkvhi, g_qkvhi);
    cudaGetSymbolAddress((void**)&qkvlo, g_qkvlo);
    cudaGetSymbolAddress((void**)&ahi,   g_ahi);
    cudaGetSymbolAddress((void**)&alo,   g_alo);

    cudaFuncSetAttribute(mma_gemm<1>,
                         cudaFuncAttributeMaxDynamicSharedMemorySize, GEMM_SMEM);
    cudaFuncSetAttribute(mma_gemm<0>,
                         cudaFuncAttributeMaxDynamicSharedMemorySize, GEMM_SMEM);
    cudaFuncSetAttribute(attn_mma,
                         cudaFuncAttributeMaxDynamicSharedMemorySize, ATT_SMEM);

    // Prep: splits + RoPE tables
    k_split<<<(SEQ * DMODEL / 4 + 255) / 256, 256>>>(x, xhi, xlo, SEQ * DMODEL / 4);
    k_split<<<(QKVDIM * DMODEL / 4 + 255) / 256, 256>>>(Wqkv, w1hi, w1lo, QKVDIM * DMODEL / 4);
    k_split<<<(DMODEL * DMODEL / 4 + 255) / 256, 256>>>(Wo, w2hi, w2lo, DMODEL * DMODEL / 4);
    k_rope_tab<<<(SEQ * 32 + 255) / 256, 256>>>(pos);

    // 1) QKV projection + RoPE + q-prescale + split store
    mma_gemm<1><<<dim3(QKVDIM / 128, SEQ / 128), 256, GEMM_SMEM>>>(
        xhi, xlo, w1hi, w1lo, nullptr, qkvhi, qkvlo, SEQ, QKVDIM, DMODEL);

    // 2) Causal flash attention (pipelined, Q-tile 128)
    attn_mma<<<dim3(SEQ / 128, NHEADS), 256, ATT_SMEM>>>();

    // 3) Output projection -> fp32 out
    mma_gemm<0><<<dim3(DMODEL / 128, SEQ / 128), 256, GEMM_SMEM>>>(
        ahi, alo, w2hi, w2lo, out, nullptr, nullptr, SEQ, DMODEL, DMODEL);
}

// round 5
// speedup vs baseline: 3.6230x; 1.0841x over previous
#include <cuda_runtime.h>
#include <cuda_bf16.h>
#include <math.h>
#include <float.h>
#include <stdint.h>

#define SEQ     4096
#define DMODEL  1024
#define NHEADS  16
#define HSIZE   64
#define QKVDIM  3072

// ---------------------------------------------------------------------------
// Scratch (__device__ globals; allocation-free rule)
// ---------------------------------------------------------------------------
__device__ __nv_bfloat16 g_xhi  [(size_t)SEQ * DMODEL];
__device__ __nv_bfloat16 g_xlo  [(size_t)SEQ * DMODEL];
__device__ __nv_bfloat16 g_w1hi [(size_t)QKVDIM * DMODEL];
__device__ __nv_bfloat16 g_w1lo [(size_t)QKVDIM * DMODEL];
__device__ __nv_bfloat16 g_w2hi [(size_t)DMODEL * DMODEL];
__device__ __nv_bfloat16 g_w2lo [(size_t)DMODEL * DMODEL];
__device__ __nv_bfloat16 g_qkvhi[(size_t)SEQ * QKVDIM];   // q(pre-scaled)|k|v, RoPE'd, split
__device__ __nv_bfloat16 g_qkvlo[(size_t)SEQ * QKVDIM];
__device__ __nv_bfloat16 g_ahi  [(size_t)SEQ * DMODEL];   // attention out, split
__device__ __nv_bfloat16 g_alo  [(size_t)SEQ * DMODEL];
__device__ float g_cos[(size_t)SEQ * 32];
__device__ float g_sin[(size_t)SEQ * 32];

// q prescale: 1/sqrt(64) * log2(e)  (exp2-domain softmax)
#define QSCALE (0.125f * 1.4426950408889634f)

// ---------------------------------------------------------------------------
// Helpers (base-ISA: mma.sync / ldmatrix / cp.async)
// ---------------------------------------------------------------------------
__device__ __forceinline__ uint32_t smem_u32(const void* p) {
    uint32_t a;
    asm("{ .reg .u64 t; cvta.to.shared.u64 t, %1; cvt.u32.u64 %0, t; }" : "=r"(a) : "l"(p));
    return a;
}
__device__ __forceinline__ void mma_bf16(float d[4], const uint32_t a[4],
                                         uint32_t b0, uint32_t b1) {
    asm volatile("mma.sync.aligned.m16n8k16.row.col.f32.bf16.bf16.f32 "
        "{%0,%1,%2,%3}, {%4,%5,%6,%7}, {%8,%9}, {%0,%1,%2,%3};"
        : "+f"(d[0]), "+f"(d[1]), "+f"(d[2]), "+f"(d[3])
        : "r"(a[0]), "r"(a[1]), "r"(a[2]), "r"(a[3]), "r"(b0), "r"(b1));
}
__device__ __forceinline__ void ldsm_x4(uint32_t r[4], uint32_t addr) {
    asm volatile("ldmatrix.sync.aligned.m8n8.x4.shared.b16 {%0,%1,%2,%3}, [%4];"
        : "=r"(r[0]), "=r"(r[1]), "=r"(r[2]), "=r"(r[3]) : "r"(addr));
}
__device__ __forceinline__ void ldsm_x4_t(uint32_t r[4], uint32_t addr) {
    asm volatile("ldmatrix.sync.aligned.m8n8.x4.trans.shared.b16 {%0,%1,%2,%3}, [%4];"
        : "=r"(r[0]), "=r"(r[1]), "=r"(r[2]), "=r"(r[3]) : "r"(addr));
}
__device__ __forceinline__ void split2(float x, float y, uint32_t& h, uint32_t& l) {
    __nv_bfloat16 hx = __float2bfloat16_rn(x), hy = __float2bfloat16_rn(y);
    __nv_bfloat16 lx = __float2bfloat16_rn(x - __bfloat162float(hx));
    __nv_bfloat16 ly = __float2bfloat16_rn(y - __bfloat162float(hy));
    __nv_bfloat162 hh(hx, hy), ll(lx, ly);
    h = *(uint32_t*)&hh;
    l = *(uint32_t*)&ll;
}
#define CP16(dst, src) asm volatile("cp.async.cg.shared.global [%0], [%1], 16;" \
                                    :: "r"(dst), "l"(src))
#define CP_COMMIT() asm volatile("cp.async.commit_group;" ::: "memory")
#define CP_WAIT2()  asm volatile("cp.async.wait_group 2;" ::: "memory")
#define CP_WAIT1()  asm volatile("cp.async.wait_group 1;" ::: "memory")
#define CP_WAIT0()  asm volatile("cp.async.wait_group 0;" ::: "memory")

// 128B rows (64 bf16): chunk c in 0..7
__device__ __forceinline__ uint32_t swz128(int row, int c) {
    return (uint32_t)(row * 128 + ((c ^ (row & 7)) << 4));
}
// 64B rows (32 bf16): chunk c in 0..3; conflict-free per 8-row ldmatrix phase
__device__ __forceinline__ uint32_t swz64(int row, int c) {
    return (uint32_t)(row * 64 + ((c ^ ((row & 7) >> 1)) << 4));
}

// ---------------------------------------------------------------------------
// Prep kernels
// ---------------------------------------------------------------------------
__global__ void k_split(const float* __restrict__ in, __nv_bfloat16* __restrict__ hi,
                        __nv_bfloat16* __restrict__ lo, int n4)
{
    int i = blockIdx.x * blockDim.x + threadIdx.x;
    if (i >= n4) return;
    float4 v = ((const float4*)in)[i];
    uint32_t h0, l0, h1, l1;
    split2(v.x, v.y, h0, l0);
    split2(v.z, v.w, h1, l1);
    ((uint32_t*)hi)[2 * i]     = h0;
    ((uint32_t*)hi)[2 * i + 1] = h1;
    ((uint32_t*)lo)[2 * i]     = l0;
    ((uint32_t*)lo)[2 * i + 1] = l1;
}

__global__ void k_rope_tab(const int* __restrict__ pos)
{
    int i = blockIdx.x * blockDim.x + threadIdx.x;
    if (i >= SEQ * 32) return;
    int m = i >> 5, k = i & 31;
    float invf = 1.0f / powf(10000.0f, (2.0f * (float)k) / 64.0f);
    float ang = (float)pos[m] * invf;
    float sn, cs;
    sincosf(ang, &sn, &cs);
    g_cos[i] = cs; g_sin[i] = sn;
}

// ---------------------------------------------------------------------------
// Projection GEMM: C[M,N] = A[M,K] @ B[N,K]^T, bf16 3-product split.
// CTA 128x128, BK=32, 3-stage cp.async pipeline, 96KB smem -> 2 CTAs/SM.
// EPI==1: RoPE + q-prescale(+log2e) + split store; EPI==0: fp32 store.
// ---------------------------------------------------------------------------
#define GARR   8192                         // 128 rows x 64B
#define GSTAGE (4 * GARR)                   // 32KB
#define GEMM_SMEM (3 * GSTAGE)              // 98304 B

template<int EPI>
__global__ __launch_bounds__(256, 2)
void mma_gemm(const __nv_bfloat16* __restrict__ Ahi, const __nv_bfloat16* __restrict__ Alo,
              const __nv_bfloat16* __restrict__ Bhi, const __nv_bfloat16* __restrict__ Blo,
              float* __restrict__ Cf, __nv_bfloat16* __restrict__ Chi,
              __nv_bfloat16* __restrict__ Clo, int M, int N, int K)
{
    extern __shared__ __nv_bfloat16 dsm[];
    const uint32_t sb = smem_u32(dsm);
    const int tid = threadIdx.x, lane = tid & 31, wid = tid >> 5;
    const int m0 = blockIdx.y * 128, n0 = blockIdx.x * 128;
    const int wm = (wid & 1) * 64, wn = (wid >> 1) * 32;

    const int arow = lane & 15,                    acol = (lane & 16) ? 1 : 0;
    const int brow = (lane & 7) + ((lane & 16) ? 8 : 0), bcol = (lane & 8) ? 1 : 0;

    float acc[4][4][4];
#pragma unroll
    for (int a = 0; a < 4; a++)
#pragma unroll
        for (int b = 0; b < 4; b++)
#pragma unroll
            for (int c = 0; c < 4; c++) acc[a][b][c] = 0.f;

    const int nk = K >> 5;

    // stage loader: 4 arrays x 128 rows x 4 chunks (16B)
    auto load_stage = [&](int kc, int s) {
        const uint32_t base = sb + (uint32_t)s * GSTAGE;
#pragma unroll
        for (int u = 0; u < 2; u++) {
            int id = tid + u * 256;
            int r = id >> 2, c = id & 3;
            uint32_t so = swz64(r, c);
            size_t ga = (size_t)(m0 + r) * K + kc + c * 8;
            size_t gb = (size_t)(n0 + r) * K + kc + c * 8;
            CP16(base +            so, Ahi + ga);
            CP16(base +     GARR + so, Alo + ga);
            CP16(base + 2 * GARR + so, Bhi + gb);
            CP16(base + 3 * GARR + so, Blo + gb);
        }
        CP_COMMIT();
    };

    load_stage(0, 0);
    load_stage(32, 1);

    for (int kc = 0; kc < nk; kc++) {
        const int cur = kc % 3;
        if (kc + 2 < nk) { load_stage((kc + 2) << 5, (kc + 2) % 3); CP_WAIT2(); }
        else if (kc + 1 < nk) { CP_WAIT1(); }
        else                  { CP_WAIT0(); }
        __syncthreads();

        const uint32_t ab = sb + (uint32_t)cur * GSTAGE;
        const uint32_t bb = ab + 2 * GARR;
#pragma unroll
        for (int ks = 0; ks < 2; ks++) {
            uint32_t ah[4][4], al[4][4];
#pragma unroll
            for (int mf = 0; mf < 4; mf++) {
                uint32_t off = swz64(wm + mf * 16 + arow, ks * 2 + acol);
                ldsm_x4(ah[mf], ab + off);
                ldsm_x4(al[mf], ab + GARR + off);
            }
#pragma unroll
            for (int np = 0; np < 2; np++) {
                uint32_t bh[4], bl[4];
                uint32_t off = swz64(wn + np * 16 + brow, ks * 2 + bcol);
                ldsm_x4(bh, bb + off);
                ldsm_x4(bl, bb + GARR + off);
#pragma unroll
                for (int sel = 0; sel < 2; sel++) {
                    const int nf = np * 2 + sel;
                    uint32_t bh0 = bh[sel * 2], bh1 = bh[sel * 2 + 1];
                    uint32_t bl0 = bl[sel * 2], bl1 = bl[sel * 2 + 1];
#pragma unroll
                    for (int mf = 0; mf < 4; mf++) {
                        mma_bf16(acc[mf][nf], ah[mf], bh0, bh1);
                        mma_bf16(acc[mf][nf], ah[mf], bl0, bl1);
                        mma_bf16(acc[mf][nf], al[mf], bh0, bh1);
                    }
                }
            }
        }
        __syncthreads();
    }

    // epilogue
#pragma unroll
    for (int mf = 0; mf < 4; mf++) {
#pragma unroll
        for (int hf = 0; hf < 2; hf++) {
            const int row = m0 + wm + mf * 16 + (lane >> 2) + hf * 8;
#pragma unroll
            for (int nf = 0; nf < 4; nf++) {
                const int col = n0 + wn + nf * 8 + (lane & 3) * 2;
                float v0 = acc[mf][nf][hf * 2], v1 = acc[mf][nf][hf * 2 + 1];
                if (EPI == 1) {
                    if (col < 2 * DMODEL) {
                        int kidx = (col & 63) >> 1;
                        float cs = g_cos[row * 32 + kidx];
                        float sn = g_sin[row * 32 + kidx];
                        float e = v0, o = v1;
                        v0 = e * cs - o * sn;
                        v1 = o * cs + e * sn;
                        if (col < DMODEL) { v0 *= QSCALE; v1 *= QSCALE; }
                    }
                    uint32_t h, l;
                    split2(v0, v1, h, l);
                    *(uint32_t*)(Chi + (size_t)row * N + col) = h;
                    *(uint32_t*)(Clo + (size_t)row * N + col) = l;
                } else {
                    *(float2*)(Cf + (size_t)row * N + col) = make_float2(v0, v1);
                }
            }
        }
    }
}

// ---------------------------------------------------------------------------
// Causal flash attention: Q-tile 128, K-tile 128 (two 64-col softmax passes),
// 8 warps, 2-stage cp.async K/V double buffer, exp2-domain softmax.
// ---------------------------------------------------------------------------
#define ATT_QARR 16384                       // 128 rows x 128B
#define ATT_KARR 16384                       // 128 rows x 128B
#define ATT_SMEM (2 * ATT_QARR + 2 * 4 * ATT_KARR)   // 163840 B

__global__ __launch_bounds__(256)
void attn_mma()
{
    extern __shared__ __nv_bfloat16 sm[];
    const uint32_t sb  = smem_u32(sm);
    const uint32_t kvb = sb + 2 * ATT_QARR;

    const int h   = blockIdx.y;
    const int qt  = gridDim.x - 1 - blockIdx.x;    // big tiles first
    const int tid = threadIdx.x;
    const int lane = tid & 31, w = tid >> 5;

    const int arow = lane & 15,                    acol = (lane & 16) ? 1 : 0;
    const int brow = (lane & 7) + ((lane & 16) ? 8 : 0), bcol = (lane & 8) ? 1 : 0;

    // async Q load (joins K/V stage-0 commit group)
    const size_t qbase = (size_t)(qt * 128) * QKVDIM + h * HSIZE;
#pragma unroll
    for (int u = 0; u < 4; u++) {
        int id = tid + u * 256;
        int r = id >> 3, c = id & 7;
        uint32_t so = swz128(r, c);
        size_t g = qbase + (size_t)r * QKVDIM + c * 8;
        CP16(sb + so,            g_qkvhi + g);
        CP16(sb + ATT_QARR + so, g_qkvlo + g);
    }

    auto load_kv = [&](int kt, int s) {
        const size_t kb = (size_t)(kt * 128) * QKVDIM + DMODEL + h * HSIZE;
        const size_t vb = kb + DMODEL;
        const uint32_t base = kvb + (uint32_t)(s * 4) * ATT_KARR;
#pragma unroll
        for (int u = 0; u < 4; u++) {
            int id = tid + u * 256;
            int r = id >> 3, c = id & 7;
            uint32_t so = swz128(r, c);
            size_t gk = kb + (size_t)r * QKVDIM + c * 8;
            size_t gv = vb + (size_t)r * QKVDIM + c * 8;
            CP16(base +                so, g_qkvhi + gk);
            CP16(base +     ATT_KARR + so, g_qkvlo + gk);
            CP16(base + 2 * ATT_KARR + so, g_qkvhi + gv);
            CP16(base + 3 * ATT_KARR + so, g_qkvlo + gv);
        }
        CP_COMMIT();
    };

    load_kv(0, 0);

    uint32_t qfh[4][4], qfl[4][4];
    float o[8][4];
#pragma unroll
    for (int i = 0; i < 8; i++)
#pragma unroll
        for (int j = 0; j < 4; j++) o[i][j] = 0.f;
    float mr[2] = { -FLT_MAX, -FLT_MAX };
    float lr[2] = { 0.f, 0.f };

    const int wrow = qt * 128 + w * 16;        // warp's first global q row

    for (int kt = 0; kt <= qt; kt++) {
        const int cur = kt & 1;
        if (kt < qt) { load_kv(kt + 1, cur ^ 1); CP_WAIT1(); }
        else         { CP_WAIT0(); }
        __syncthreads();

        if (kt == 0) {
#pragma unroll
            for (int t = 0; t < 4; t++) {
                uint32_t off = swz128(w * 16 + arow, t * 2 + acol);
                ldsm_x4(qfh[t], sb + off);
                ldsm_x4(qfl[t], sb + ATT_QARR + off);
            }
        }

        const uint32_t kbh = kvb + (uint32_t)(cur * 4) * ATT_KARR;
        const uint32_t kbl = kbh + ATT_KARR;
        const uint32_t vbh = kbh + 2 * ATT_KARR;
        const uint32_t vbl = kbh + 3 * ATT_KARR;

#pragma unroll
        for (int half = 0; half < 2; half++) {
            const int colbase = kt * 128 + half * 64;
            if (colbase > wrow + 15) continue;       // fully masked for this warp
            const int rbase = half * 64;             // k-row offset inside the tile

            float s[8][4];
#pragma unroll
            for (int i = 0; i < 8; i++)
#pragma unroll
                for (int j = 0; j < 4; j++) s[i][j] = 0.f;

            // S = Q' K^T (scale+log2e pre-folded into Q)
#pragma unroll
            for (int t = 0; t < 4; t++) {
#pragma unroll
                for (int np = 0; np < 4; np++) {
                    uint32_t bh[4], bl[4];
                    uint32_t off = swz128(rbase + np * 16 + brow, t * 2 + bcol);
                    ldsm_x4(bh, kbh + off);
                    ldsm_x4(bl, kbl + off);
#pragma unroll
                    for (int sel = 0; sel < 2; sel++) {
                        const int nf = np * 2 + sel;
                        uint32_t b0h = bh[sel * 2], b1h = bh[sel * 2 + 1];
                        uint32_t b0l = bl[sel * 2], b1l = bl[sel * 2 + 1];
                        mma_bf16(s[nf], qfh[t], b0h, b1h);
                        mma_bf16(s[nf], qfh[t], b0l, b1l);
                        mma_bf16(s[nf], qfl[t], b0h, b1h);
                    }
                }
            }

            // causal mask (only if this half crosses the warp's rows)
            if (colbase + 63 > wrow) {
                const int r0 = wrow + (lane >> 2), r1 = r0 + 8;
                const int cb = colbase + (lane & 3) * 2;
#pragma unroll
                for (int nf = 0; nf < 8; nf++) {
                    const int c0 = cb + nf * 8;
                    if (c0     > r0) s[nf][0] = -FLT_MAX;
                    if (c0 + 1 > r0) s[nf][1] = -FLT_MAX;
                    if (c0     > r1) s[nf][2] = -FLT_MAX;
                    if (c0 + 1 > r1) s[nf][3] = -FLT_MAX;
                }
            }

            // online softmax per row-half (exp2 domain)
#pragma unroll
            for (int hf = 0; hf < 2; hf++) {
                float rm = -FLT_MAX;
#pragma unroll
                for (int nf = 0; nf < 8; nf++)
                    rm = fmaxf(rm, fmaxf(s[nf][hf * 2], s[nf][hf * 2 + 1]));
                rm = fmaxf(rm, __shfl_xor_sync(0xffffffffu, rm, 1));
                rm = fmaxf(rm, __shfl_xor_sync(0xffffffffu, rm, 2));

                float mn   = fmaxf(mr[hf], rm);
                float corr = exp2f(mr[hf] - mn);
                mr[hf] = mn;

                float rs = 0.f;
#pragma unroll
                for (int nf = 0; nf < 8; nf++) {
                    float p0 = exp2f(s[nf][hf * 2]     - mn);
                    float p1 = exp2f(s[nf][hf * 2 + 1] - mn);
                    s[nf][hf * 2]     = p0;
                    s[nf][hf * 2 + 1] = p1;
                    rs += p0 + p1;
                }
                rs += __shfl_xor_sync(0xffffffffu, rs, 1);
                rs += __shfl_xor_sync(0xffffffffu, rs, 2);

                lr[hf] = lr[hf] * corr + rs;
#pragma unroll
                for (int df = 0; df < 8; df++) {
                    o[df][hf * 2]     *= corr;
                    o[df][hf * 2 + 1] *= corr;
                }
            }

            // O += P V (P re-split in-register; V via ldmatrix.trans)
#pragma unroll
            for (int t = 0; t < 4; t++) {
                uint32_t ph[4], pl[4];
                split2(s[2 * t][0],     s[2 * t][1],     ph[0], pl[0]);
                split2(s[2 * t][2],     s[2 * t][3],     ph[1], pl[1]);
                split2(s[2 * t + 1][0], s[2 * t + 1][1], ph[2], pl[2]);
                split2(s[2 * t + 1][2], s[2 * t + 1][3], ph[3], pl[3]);
#pragma unroll
                for (int np = 0; np < 4; np++) {
                    uint32_t vh4[4], vl4[4];
                    uint32_t off = swz128(rbase + t * 16 + arow, np * 2 + acol);
                    ldsm_x4_t(vh4, vbh + off);
                    ldsm_x4_t(vl4, vbl + off);
#pragma unroll
                    for (int sel = 0; sel < 2; sel++) {
                        const int df = np * 2 + sel;
                        uint32_t v0h = vh4[sel * 2], v1h = vh4[sel * 2 + 1];
                        uint32_t v0l = vl4[sel * 2], v1l = vl4[sel * 2 + 1];
                        mma_bf16(o[df], ph, v0h, v1h);
                        mma_bf16(o[df], ph, v0l, v1l);
                        mma_bf16(o[df], pl, v0h, v1h);
                    }
                }
            }
        }
        __syncthreads();
    }

    // epilogue: normalize, split, store for the O-projection
#pragma unroll
    for (int hf = 0; hf < 2; hf++) {
        const float inv = 1.0f / lr[hf];
        const int row = wrow + (lane >> 2) + hf * 8;
#pragma unroll
        for (int df = 0; df < 8; df++) {
            const int col = h * 64 + df * 8 + (lane & 3) * 2;
            float v0 = o[df][hf * 2] * inv, v1 = o[df][hf * 2 + 1] * inv;
            uint32_t hh, ll;
            split2(v0, v1, hh, ll);
            *(uint32_t*)(g_ahi + (size_t)row * DMODEL + col) = hh;
            *(uint32_t*)(g_alo + (size_t)row * DMODEL + col) = ll;
        }
    }
}

// ---------------------------------------------------------------------------
extern "C" void kernel_launch(void* const* d_in, const int* in_sizes, int n_in,
                              void* d_out, int out_size)
{
    const float* x    = (const float*)d_in[0];
    const int*   pos  = (const int*)  d_in[1];
    const float* Wqkv = (const float*)d_in[2];
    const float* Wo   = (const float*)d_in[3];
    float*       out  = (float*)d_out;

    __nv_bfloat16 *xhi, *xlo, *w1hi, *w1lo, *w2hi, *w2lo, *qkvhi, *qkvlo, *ahi, *alo;
    cudaGetSymbolAddress((void**)&xhi,   g_xhi);
    cudaGetSymbolAddress((void**)&xlo,   g_xlo);
    cudaGetSymbolAddress((void**)&w1hi,  g_w1hi);
    cudaGetSymbolAddress((void**)&w1lo,  g_w1lo);
    cudaGetSymbolAddress((void**)&w2hi,  g_w2hi);
    cudaGetSymbolAddress((void**)&w2lo,  g_w2lo);
    cudaGetSymbolAddress((void**)&qkvhi, g_qkvhi);
    cudaGetSymbolAddress((void**)&qkvlo, g_qkvlo);
    cudaGetSymbolAddress((void**)&ahi,   g_ahi);
    cudaGetSymbolAddress((void**)&alo,   g_alo);

    cudaFuncSetAttribute(mma_gemm<1>,
                         cudaFuncAttributeMaxDynamicSharedMemorySize, GEMM_SMEM);
    cudaFuncSetAttribute(mma_gemm<0>,
                         cudaFuncAttributeMaxDynamicSharedMemorySize, GEMM_SMEM);
    cudaFuncSetAttribute(attn_mma,
                         cudaFuncAttributeMaxDynamicSharedMemorySize, ATT_SMEM);

    // Prep: splits + RoPE tables
    k_split<<<(SEQ * DMODEL / 4 + 255) / 256, 256>>>(x, xhi, xlo, SEQ * DMODEL / 4);
    k_split<<<(QKVDIM * DMODEL / 4 + 255) / 256, 256>>>(Wqkv, w1hi, w1lo, QKVDIM * DMODEL / 4);
    k_split<<<(DMODEL * DMODEL / 4 + 255) / 256, 256>>>(Wo, w2hi, w2lo, DMODEL * DMODEL / 4);
    k_rope_tab<<<(SEQ * 32 + 255) / 256, 256>>>(pos);

    // 1) QKV projection + RoPE + q-prescale + split store
    mma_gemm<1><<<dim3(QKVDIM / 128, SEQ / 128), 256, GEMM_SMEM>>>(
        xhi, xlo, w1hi, w1lo, nullptr, qkvhi, qkvlo, SEQ, QKVDIM, DMODEL);

    // 2) Causal flash attention (K-tile 128, pipelined)
    attn_mma<<<dim3(SEQ / 128, NHEADS), 256, ATT_SMEM>>>();

    // 3) Output projection -> fp32 out
    mma_gemm<0><<<dim3(DMODEL / 128, SEQ / 128), 256, GEMM_SMEM>>>(
        ahi, alo, w2hi, w2lo, out, nullptr, nullptr, SEQ, DMODEL, DMODEL);
}